// round 2
// baseline (speedup 1.0000x reference)
#include <cuda_runtime.h>

#define C_CH 32
#define HW   256
#define KS2  9
#define QS   32    // coarse spatial size after pool
#define NB   4

// Scratch (no allocations allowed in kernel_launch)
__device__ float g_p[NB * C_CH * QS * QS];   // [n][c][32][32] pooled coarse features

// ---------------------------------------------------------------------------
// Kernel A: psf [4,32,256,256] -> bilinear 1/4 (exact: weights all 0.25,
// src = 4u+1.5 so samples are avg of a fixed 2x2) -> maxpool2 -> p [4,32,32,32]
// All 16 loads explicitly batched before arithmetic (MLP=16).
// ---------------------------------------------------------------------------
__global__ void kA(const float* __restrict__ psf) {
    int t = blockIdx.x * blockDim.x + threadIdx.x;   // 4*32*32*32 = 131072
    int j = t & 31;
    int i = (t >> 5) & 31;
    int c = (t >> 10) & 31;
    int n = t >> 15;
    const float* base = psf + ((size_t)(n * C_CH + c) * HW) * HW;

    const int rr[4] = {8 * i + 1, 8 * i + 2, 8 * i + 5, 8 * i + 6};
    const int cc[4] = {8 * j + 1, 8 * j + 2, 8 * j + 5, 8 * j + 6};

    float v[4][4];
#pragma unroll
    for (int a = 0; a < 4; a++) {
#pragma unroll
        for (int b = 0; b < 4; b++) {
            v[a][b] = __ldg(base + rr[a] * HW + cc[b]);
        }
    }
    float s00 = v[0][0] + v[0][1] + v[1][0] + v[1][1];
    float s01 = v[0][2] + v[0][3] + v[1][2] + v[1][3];
    float s10 = v[2][0] + v[2][1] + v[3][0] + v[3][1];
    float s11 = v[2][2] + v[2][3] + v[3][2] + v[3][3];
    g_p[t] = 0.25f * fmaxf(fmaxf(s00, s01), fmaxf(s10, s11));
}

// ---------------------------------------------------------------------------
// Kernel C (fused): per-block 1x1-conv filter generation (ex-kB) + x8
// bilinear upsample + FAC 3x3 dynamic filtering.
// Block: (16 output rows) x (256-wide row) for one (n, c).
// ---------------------------------------------------------------------------
__global__ void __launch_bounds__(256) kC(const float* __restrict__ fm,
                                          const float* __restrict__ w1,
                                          const float* __restrict__ b1,
                                          const float* __restrict__ ws,
                                          const float* __restrict__ bs,
                                          float* __restrict__ out) {
    __shared__ float fmt[18][258];       // fm tile rows h0-1..h0+16, cols -1..256
    __shared__ float yt[KS2][4][32];     // 9 taps x 4 coarse rows x 32 coarse cols

    const int tt = blockIdx.x;           // 0..15  (16-row tiles)
    const int c  = blockIdx.y;           // 0..31
    const int n  = blockIdx.z;           // 0..3
    const int w  = threadIdx.x;          // 0..255 (one output column per thread)
    const int h0 = tt * 16;
    const int crBase = 2 * tt - 1;

    // ---- stage featuremap tile (zero padded ring) ----
    const float* fbase = fm + ((size_t)(n * C_CH + c) * HW) * HW;
#pragma unroll
    for (int r = 0; r < 18; r++) {
        int gh = h0 - 1 + r;
        bool rowok = (gh >= 0) && (gh < HW);
#pragma unroll
        for (int col = w; col < 258; col += 256) {
            int gw = col - 1;
            float v = 0.f;
            if (rowok && gw >= 0 && gw < HW) v = fbase[gh * HW + gw];
            fmt[r][col] = v;
        }
    }

    // ---- compute coarse filter tile in-block (fused ex-kB) ----
    // thread -> (kgrp, r, col): kgrp = w>>7 (k 0..4 | 5..8), r = (w>>5)&3, col = w&31
    {
        const int kgrp = w >> 7;
        const int r    = (w >> 5) & 3;
        const int col  = w & 31;
        int cr = crBase + r;
        cr = min(max(cr, 0), QS - 1);

        // cache this thread's p column across channels in registers
        float pv[C_CH];
        const float* pb = g_p + (size_t)n * (C_CH * QS * QS) + cr * QS + col;
#pragma unroll
        for (int ch = 0; ch < C_CH; ch++) pv[ch] = pb[ch * (QS * QS)];

        const int kbeg = kgrp ? 5 : 0;
        const int kend = kgrp ? 9 : 5;
        for (int k = kbeg; k < kend; k++) {
            const int o = c * KS2 + k;
            const float* wr1 = w1 + o * C_CH;
            const float* wrs = ws + o * C_CH;
            float a1 = 0.f, a2 = 0.f;
#pragma unroll
            for (int ch = 0; ch < C_CH; ch++) {
                a1 = fmaf(pv[ch], __ldg(wr1 + ch), a1);
                a2 = fmaf(pv[ch], __ldg(wrs + ch), a2);
            }
            a1 += b1[o];
            a2 += bs[o];
            float act = (a1 >= 0.f) ? a1 : 0.2f * a1;
            yt[k][r][col] = act + a2;
        }
    }
    __syncthreads();

    // ---- per-thread horizontal lerp of all 4 staged rows x 9 taps ----
    int ix0 = (w - 4) >> 3;                       // arithmetic shift: floors
    float wx = (float)w * 0.125f - 0.4375f - (float)ix0;
    int jx0 = max(ix0, 0);
    int jx1 = min(ix0 + 1, QS - 1);
    float hl[4][KS2];
#pragma unroll
    for (int r = 0; r < 4; r++) {
#pragma unroll
        for (int k = 0; k < KS2; k++) {
            float a = yt[k][r][jx0];
            float b = yt[k][r][jx1];
            hl[r][k] = a + wx * (b - a);
        }
    }

    // ---- rolling 3x3 featuremap window + two-dot vertical lerp ----
    float win[3][3];
#pragma unroll
    for (int d = 0; d < 3; d++) {
        win[0][d] = fmt[0][w + d];
        win[1][d] = fmt[1][w + d];
    }

    float* obase = out + (((size_t)(n * C_CH + c) * HW + h0) * HW) + w;

#pragma unroll
    for (int hh = 0; hh < 16; hh++) {
#pragma unroll
        for (int d = 0; d < 3; d++) win[2][d] = fmt[hh + 2][w + d];

        const int t0 = (hh < 4) ? 0 : ((hh < 12) ? 1 : 2);
        const float wy = (float)hh * 0.125f + 0.5625f - (float)t0;

        float dot0 = 0.f, dot1 = 0.f;
#pragma unroll
        for (int dy = 0; dy < 3; dy++) {
#pragma unroll
            for (int dx = 0; dx < 3; dx++) {
                int k = dy * 3 + dx;
                dot0 = fmaf(hl[t0][k], win[dy][dx], dot0);
                dot1 = fmaf(hl[t0 + 1][k], win[dy][dx], dot1);
            }
        }
        obase[hh * HW] = dot0 + wy * (dot1 - dot0);

#pragma unroll
        for (int d = 0; d < 3; d++) {
            win[0][d] = win[1][d];
            win[1][d] = win[2][d];
        }
    }
}

// ---------------------------------------------------------------------------
extern "C" void kernel_launch(void* const* d_in, const int* in_sizes, int n_in,
                              void* d_out, int out_size) {
    const float* psf = (const float*)d_in[0];
    const float* fm  = (const float*)d_in[1];
    const float* w1  = (const float*)d_in[2];
    const float* b1  = (const float*)d_in[3];
    const float* ws  = (const float*)d_in[4];
    const float* bs  = (const float*)d_in[5];
    float* out = (float*)d_out;

    kA<<<512, 256>>>(psf);                 // 131072 threads
    dim3 gc(16, C_CH, NB);
    kC<<<gc, 256>>>(fm, w1, b1, ws, bs, out);
}